// round 1
// baseline (speedup 1.0000x reference)
#include <cuda_runtime.h>
#include <cstdint>

#define NN 50000
#define DD 64
#define NE 800000

// Scratch (allocation-free rule: __device__ globals)
__device__ int   g_src[NE];
__device__ int   g_dst[NE];
__device__ float g_t[NN * DD];   // t = x @ W_nbr for current layer
__device__ float g_h[NN * DD];   // hidden activations (pre-relu accumulate)
__device__ int   g_idx64;        // 1 if edge_index stored as int64

// ---------------------------------------------------------------------------
// Detect whether edge_index buffer is int64 or int32.
// If int64 (little-endian), every odd 32-bit word is a high half == 0
// (indices are in [0, 50000)). If int32, odd words are real indices —
// probability all 128 sampled are zero is (1/50000)^128 ~ 0.
// ---------------------------------------------------------------------------
__global__ void detect_kernel(const unsigned* __restrict__ words) {
    __shared__ int any_nonzero;
    if (threadIdx.x == 0) any_nonzero = 0;
    __syncthreads();
    unsigned w = words[2 * threadIdx.x + 1];   // words 1,3,...,255
    if (w != 0u) any_nonzero = 1;              // benign race
    __syncthreads();
    if (threadIdx.x == 0) g_idx64 = any_nonzero ? 0 : 1;
}

__global__ void convert_kernel(const void* __restrict__ idx, int E) {
    int i = blockIdx.x * blockDim.x + threadIdx.x;
    if (i >= E) return;
    if (g_idx64) {
        const long long* p = (const long long*)idx;
        g_src[i] = (int)p[i];
        g_dst[i] = (int)p[(size_t)E + i];
    } else {
        const int* p = (const int*)idx;
        g_src[i] = p[i];
        g_dst[i] = p[(size_t)E + i];
    }
}

// ---------------------------------------------------------------------------
// Dual GEMM: Omain = act(X) @ Wroot + bias ;  Ot = act(X) @ Wnbr
// act = relu if RELU. 32 rows per block, 256 threads (8 threads per row,
// each thread computes 8 root cols + 8 nbr cols).
// Both 64x64 weight matrices staged in smem (32KB) + 32x68 X tile (padded
// stride 68 to break the 64-stride bank conflict on the xv broadcast load).
// ---------------------------------------------------------------------------
template <bool RELU>
__global__ void __launch_bounds__(256) gemm_dual_kernel(
    const float* __restrict__ X,
    const float* __restrict__ Wroot,
    const float* __restrict__ Wnbr,
    const float* __restrict__ bias,
    float* __restrict__ Omain,
    float* __restrict__ Ot,
    int n)
{
    __shared__ float sWr[64 * 64];
    __shared__ float sWn[64 * 64];
    __shared__ float sB[64];
    __shared__ float sX[32 * 68];

    const int tid = threadIdx.x;

    // Stage weights: 1024 float4 each, 4 per thread
    {
        const float4* wr4 = (const float4*)Wroot;
        const float4* wn4 = (const float4*)Wnbr;
        float4* swr4 = (float4*)sWr;
        float4* swn4 = (float4*)sWn;
#pragma unroll
        for (int i = 0; i < 4; i++) {
            swr4[tid + 256 * i] = wr4[tid + 256 * i];
            swn4[tid + 256 * i] = wn4[tid + 256 * i];
        }
        if (tid < 64) sB[tid] = bias[tid];
    }

    const int row0 = blockIdx.x * 32;

    // Stage 32 rows of X (with optional relu), 512 float4 total, 2 per thread
#pragma unroll
    for (int i = 0; i < 2; i++) {
        int idx = tid + 256 * i;          // 0..511
        int r = idx >> 4;                 // local row
        int c4 = idx & 15;                // float4 chunk in row
        int grow = row0 + r;
        float4 v = make_float4(0.f, 0.f, 0.f, 0.f);
        if (grow < n) v = ((const float4*)X)[(size_t)grow * 16 + c4];
        if (RELU) {
            v.x = fmaxf(v.x, 0.f); v.y = fmaxf(v.y, 0.f);
            v.z = fmaxf(v.z, 0.f); v.w = fmaxf(v.w, 0.f);
        }
        *(float4*)&sX[r * 68 + c4 * 4] = v;
    }
    __syncthreads();

    const int r = tid >> 3;      // 0..31 local row
    const int cseg = tid & 7;    // 0..7 -> cols [cseg*8, cseg*8+8)

    float4 ar0 = *(const float4*)&sB[cseg * 8];
    float4 ar1 = *(const float4*)&sB[cseg * 8 + 4];
    float4 an0 = make_float4(0.f, 0.f, 0.f, 0.f);
    float4 an1 = make_float4(0.f, 0.f, 0.f, 0.f);

    const float* xrow = &sX[r * 68];

#pragma unroll
    for (int k = 0; k < 64; k++) {
        float xv = xrow[k];
        float4 wr0 = *(const float4*)&sWr[k * 64 + cseg * 8];
        float4 wr1 = *(const float4*)&sWr[k * 64 + cseg * 8 + 4];
        float4 wn0 = *(const float4*)&sWn[k * 64 + cseg * 8];
        float4 wn1 = *(const float4*)&sWn[k * 64 + cseg * 8 + 4];
        ar0.x = fmaf(xv, wr0.x, ar0.x); ar0.y = fmaf(xv, wr0.y, ar0.y);
        ar0.z = fmaf(xv, wr0.z, ar0.z); ar0.w = fmaf(xv, wr0.w, ar0.w);
        ar1.x = fmaf(xv, wr1.x, ar1.x); ar1.y = fmaf(xv, wr1.y, ar1.y);
        ar1.z = fmaf(xv, wr1.z, ar1.z); ar1.w = fmaf(xv, wr1.w, ar1.w);
        an0.x = fmaf(xv, wn0.x, an0.x); an0.y = fmaf(xv, wn0.y, an0.y);
        an0.z = fmaf(xv, wn0.z, an0.z); an0.w = fmaf(xv, wn0.w, an0.w);
        an1.x = fmaf(xv, wn1.x, an1.x); an1.y = fmaf(xv, wn1.y, an1.y);
        an1.z = fmaf(xv, wn1.z, an1.z); an1.w = fmaf(xv, wn1.w, an1.w);
    }

    int grow = row0 + r;
    if (grow < n) {
        float4* om = (float4*)(Omain + (size_t)grow * 64 + cseg * 8);
        om[0] = ar0; om[1] = ar1;
        float4* ot = (float4*)(Ot + (size_t)grow * 64 + cseg * 8);
        ot[0] = an0; ot[1] = an1;
    }
}

// ---------------------------------------------------------------------------
// Edge scatter: out[dst] += t[src], vectorized red.global.add.v4.f32.
// 16 threads per edge, each handles one float4 of the 64-float row.
// ---------------------------------------------------------------------------
__global__ void __launch_bounds__(256) scatter_kernel(
    const float* __restrict__ t, float* __restrict__ out, int E)
{
    int gid = blockIdx.x * blockDim.x + threadIdx.x;
    int e = gid >> 4;
    if (e >= E) return;
    int part = gid & 15;
    int s = g_src[e];
    int d = g_dst[e];
    float4 v = ((const float4*)(t + (size_t)s * 64))[part];
    float* dp = out + (size_t)d * 64 + part * 4;
    asm volatile("red.global.add.v4.f32 [%0], {%1, %2, %3, %4};"
                 :: "l"(dp), "f"(v.x), "f"(v.y), "f"(v.z), "f"(v.w)
                 : "memory");
}

// ---------------------------------------------------------------------------
extern "C" void kernel_launch(void* const* d_in, const int* in_sizes, int n_in,
                              void* d_out, int out_size)
{
    const float* x      = (const float*)d_in[0];
    const void*  eidx   = d_in[1];
    const float* W1root = (const float*)d_in[2];
    const float* W1nbr  = (const float*)d_in[3];
    const float* b1     = (const float*)d_in[4];
    const float* W2root = (const float*)d_in[5];
    const float* W2nbr  = (const float*)d_in[6];
    const float* b2     = (const float*)d_in[7];
    float* out = (float*)d_out;

    const int n = in_sizes[0] / DD;        // 50000
    const int E = in_sizes[1] / 2;         // 800000 (element count same for i32/i64)

    float *hptr, *tptr;
    cudaGetSymbolAddress((void**)&hptr, g_h);
    cudaGetSymbolAddress((void**)&tptr, g_t);

    const int gemm_blocks = (n + 31) / 32;
    const int conv_blocks = (E + 255) / 256;
    const long long sthreads = (long long)E * 16;
    const int scat_blocks = (int)((sthreads + 255) / 256);

    detect_kernel<<<1, 128>>>((const unsigned*)eidx);
    convert_kernel<<<conv_blocks, 256>>>(eidx, E);

    // Layer 1: h = x@W1root + b1 ; t = x@W1nbr ; then h += scatter(t)
    gemm_dual_kernel<false><<<gemm_blocks, 256>>>(x, W1root, W1nbr, b1, hptr, tptr, n);
    scatter_kernel<<<scat_blocks, 256>>>(tptr, hptr, E);

    // Layer 2: out = relu(h)@W2root + b2 ; t = relu(h)@W2nbr ; out += scatter(t)
    gemm_dual_kernel<true><<<gemm_blocks, 256>>>(hptr, W2root, W2nbr, b2, out, tptr, n);
    scatter_kernel<<<scat_blocks, 256>>>(tptr, out, E);
}

// round 4
// speedup vs baseline: 1.9317x; 1.9317x over previous
#include <cuda_runtime.h>
#include <cstdint>

#define NN 50000
#define DD 64
#define NE 800000

// ---- scratch (__device__ globals; allocation-free rule) ----
__device__ int   g_src[NE];
__device__ int   g_dst[NE];
__device__ int   g_csrc[NE];     // CSR: source node per edge, grouped by dst
__device__ int   g_deg[NN];
__device__ int   g_off[NN + 1];
__device__ int   g_cur[NN];
__device__ int   g_bsum[256];
__device__ __align__(16) float g_t[NN * DD];   // t = act(X) @ W_nbr
__device__ __align__(16) float g_h[NN * DD];   // hidden activations
__device__ int   g_idx64;

// ---------------------------------------------------------------------------
// int64 vs int32 edge_index detection (odd 32-bit words all zero => int64)
// ---------------------------------------------------------------------------
__global__ void detect_kernel(const unsigned* __restrict__ words) {
    __shared__ int any_nonzero;
    if (threadIdx.x == 0) any_nonzero = 0;
    __syncthreads();
    if (words[2 * threadIdx.x + 1] != 0u) any_nonzero = 1;
    __syncthreads();
    if (threadIdx.x == 0) g_idx64 = any_nonzero ? 0 : 1;
}

__global__ void zero_deg_kernel() {
    int i = blockIdx.x * blockDim.x + threadIdx.x;
    if (i < NN) g_deg[i] = 0;
}

// convert indices to int32 + histogram of dst degrees
__global__ void convert_hist_kernel(const void* __restrict__ idx, int E) {
    int i = blockIdx.x * blockDim.x + threadIdx.x;
    if (i >= E) return;
    int s, d;
    if (g_idx64) {
        const long long* p = (const long long*)idx;
        s = (int)p[i];
        d = (int)p[(size_t)E + i];
    } else {
        const int* p = (const int*)idx;
        s = p[i];
        d = p[(size_t)E + i];
    }
    g_src[i] = s;
    g_dst[i] = d;
    atomicAdd(&g_deg[d], 1);
}

// ---- 3-phase exclusive scan of g_deg -> g_off ----
__global__ void scan1_kernel() {
    __shared__ int sh[256];
    int tid = threadIdx.x;
    int i = blockIdx.x * 256 + tid;
    int v = (i < NN) ? g_deg[i] : 0;
    sh[tid] = v;
    __syncthreads();
#pragma unroll
    for (int off = 1; off < 256; off <<= 1) {
        int x = (tid >= off) ? sh[tid - off] : 0;
        __syncthreads();
        sh[tid] += x;
        __syncthreads();
    }
    if (i < NN) g_off[i] = sh[tid] - v;          // exclusive within block
    if (tid == 255) g_bsum[blockIdx.x] = sh[255];
}

__global__ void scan2_kernel(int nb) {
    __shared__ int sh[256];
    int tid = threadIdx.x;
    int v = (tid < nb) ? g_bsum[tid] : 0;
    sh[tid] = v;
    __syncthreads();
#pragma unroll
    for (int off = 1; off < 256; off <<= 1) {
        int x = (tid >= off) ? sh[tid - off] : 0;
        __syncthreads();
        sh[tid] += x;
        __syncthreads();
    }
    if (tid < nb) g_bsum[tid] = sh[tid] - v;     // exclusive block offsets
}

__global__ void scan3_kernel() {
    int i = blockIdx.x * 256 + threadIdx.x;
    if (i < NN) {
        int o = g_off[i] + g_bsum[blockIdx.x];
        g_off[i] = o;
        g_cur[i] = o;
    }
    if (i == 0) g_off[NN] = NE;
}

__global__ void fill_kernel(int E) {
    int e = blockIdx.x * blockDim.x + threadIdx.x;
    if (e >= E) return;
    int d = g_dst[e];
    int p = atomicAdd(&g_cur[d], 1);
    g_csrc[p] = g_src[e];
}

// ---------------------------------------------------------------------------
// Dual GEMM: Omain = act(X)@Wroot + b ; Ot = act(X)@Wnbr
// 128 rows/block, 256 threads. Thread tile: 4 rows x 8 cols x 2 matrices.
// X staged TRANSPOSED (sXT[k][r], stride 132 — 16B-aligned float4 reads,
// 528k byte base keeps alignment for every k). 5 LDS.128 per 64 FFMA.
// ---------------------------------------------------------------------------
#define XT_STRIDE 132

template <bool RELU>
__global__ void __launch_bounds__(256, 2) gemm_dual_kernel(
    const float* __restrict__ X,
    const float* __restrict__ Wroot,
    const float* __restrict__ Wnbr,
    const float* __restrict__ bias,
    float* __restrict__ Omain,
    float* __restrict__ Ot,
    int n)
{
    __shared__ __align__(16) float sWr[64 * 64];
    __shared__ __align__(16) float sWn[64 * 64];
    __shared__ __align__(16) float sB[64];
    __shared__ __align__(16) float sXT[64 * XT_STRIDE];   // [k][row]

    const int tid = threadIdx.x;
    const int row0 = blockIdx.x * 128;

    // stage weights (1024 float4 each -> 4 per thread)
    {
        const float4* wr4 = (const float4*)Wroot;
        const float4* wn4 = (const float4*)Wnbr;
        float4* swr4 = (float4*)sWr;
        float4* swn4 = (float4*)sWn;
#pragma unroll
        for (int i = 0; i < 4; i++) {
            swr4[tid + 256 * i] = wr4[tid + 256 * i];
            swn4[tid + 256 * i] = wn4[tid + 256 * i];
        }
        if (tid < 64) sB[tid] = bias[tid];
    }

    // stage X transposed: 128 rows x 16 float4-chunks = 2048 chunks, 8/thread
#pragma unroll
    for (int i = 0; i < 8; i++) {
        int idx = tid + 256 * i;      // 0..2047
        int r = idx >> 4;             // local row 0..127
        int c4 = idx & 15;            // float4 chunk 0..15
        int grow = row0 + r;
        float4 v = make_float4(0.f, 0.f, 0.f, 0.f);
        if (grow < n) v = ((const float4*)X)[(size_t)grow * 16 + c4];
        if (RELU) {
            v.x = fmaxf(v.x, 0.f); v.y = fmaxf(v.y, 0.f);
            v.z = fmaxf(v.z, 0.f); v.w = fmaxf(v.w, 0.f);
        }
        sXT[(c4 * 4 + 0) * XT_STRIDE + r] = v.x;
        sXT[(c4 * 4 + 1) * XT_STRIDE + r] = v.y;
        sXT[(c4 * 4 + 2) * XT_STRIDE + r] = v.z;
        sXT[(c4 * 4 + 3) * XT_STRIDE + r] = v.w;
    }
    __syncthreads();

    const int cseg = tid & 7;        // column segment: cols [cseg*8, cseg*8+8)
    const int rowgrp = tid >> 3;     // 0..31 -> rows [rowgrp*4, rowgrp*4+4)

    float4 ar[4][2], an[4][2];
    {
        float4 b0 = *(const float4*)&sB[cseg * 8];
        float4 b1 = *(const float4*)&sB[cseg * 8 + 4];
#pragma unroll
        for (int j = 0; j < 4; j++) {
            ar[j][0] = b0; ar[j][1] = b1;
            an[j][0] = make_float4(0.f, 0.f, 0.f, 0.f);
            an[j][1] = make_float4(0.f, 0.f, 0.f, 0.f);
        }
    }

#pragma unroll 8
    for (int k = 0; k < 64; k++) {
        float4 xv = *(const float4*)&sXT[k * XT_STRIDE + rowgrp * 4];
        float4 wr0 = *(const float4*)&sWr[k * 64 + cseg * 8];
        float4 wr1 = *(const float4*)&sWr[k * 64 + cseg * 8 + 4];
        float4 wn0 = *(const float4*)&sWn[k * 64 + cseg * 8];
        float4 wn1 = *(const float4*)&sWn[k * 64 + cseg * 8 + 4];
        const float xs[4] = {xv.x, xv.y, xv.z, xv.w};
#pragma unroll
        for (int j = 0; j < 4; j++) {
            float xvj = xs[j];
            ar[j][0].x = fmaf(xvj, wr0.x, ar[j][0].x);
            ar[j][0].y = fmaf(xvj, wr0.y, ar[j][0].y);
            ar[j][0].z = fmaf(xvj, wr0.z, ar[j][0].z);
            ar[j][0].w = fmaf(xvj, wr0.w, ar[j][0].w);
            ar[j][1].x = fmaf(xvj, wr1.x, ar[j][1].x);
            ar[j][1].y = fmaf(xvj, wr1.y, ar[j][1].y);
            ar[j][1].z = fmaf(xvj, wr1.z, ar[j][1].z);
            ar[j][1].w = fmaf(xvj, wr1.w, ar[j][1].w);
            an[j][0].x = fmaf(xvj, wn0.x, an[j][0].x);
            an[j][0].y = fmaf(xvj, wn0.y, an[j][0].y);
            an[j][0].z = fmaf(xvj, wn0.z, an[j][0].z);
            an[j][0].w = fmaf(xvj, wn0.w, an[j][0].w);
            an[j][1].x = fmaf(xvj, wn1.x, an[j][1].x);
            an[j][1].y = fmaf(xvj, wn1.y, an[j][1].y);
            an[j][1].z = fmaf(xvj, wn1.z, an[j][1].z);
            an[j][1].w = fmaf(xvj, wn1.w, an[j][1].w);
        }
    }

#pragma unroll
    for (int j = 0; j < 4; j++) {
        int grow = row0 + rowgrp * 4 + j;
        if (grow < n) {
            float4* om = (float4*)(Omain + (size_t)grow * 64 + cseg * 8);
            om[0] = ar[j][0]; om[1] = ar[j][1];
            float4* ot = (float4*)(Ot + (size_t)grow * 64 + cseg * 8);
            ot[0] = an[j][0]; ot[1] = an[j][1];
        }
    }
}

// ---------------------------------------------------------------------------
// CSR gather-aggregate: one warp per node.
// out[i] += sum_{e: dst==i} t[csrc[e]]   (float2 per lane, unroll-4 for MLP)
// ---------------------------------------------------------------------------
__global__ void __launch_bounds__(256) agg_kernel(
    const float* __restrict__ t, float* __restrict__ out, int n)
{
    int gid = blockIdx.x * blockDim.x + threadIdx.x;
    int node = gid >> 5;
    if (node >= n) return;
    int lane = threadIdx.x & 31;

    int start = g_off[node];
    int end   = g_off[node + 1];

    const float2* t2 = (const float2*)t;
    float ax = 0.f, ay = 0.f;

    int j = start;
    for (; j + 4 <= end; j += 4) {
        int s0 = __ldg(&g_csrc[j]);
        int s1 = __ldg(&g_csrc[j + 1]);
        int s2 = __ldg(&g_csrc[j + 2]);
        int s3 = __ldg(&g_csrc[j + 3]);
        float2 v0 = t2[s0 * 32 + lane];
        float2 v1 = t2[s1 * 32 + lane];
        float2 v2 = t2[s2 * 32 + lane];
        float2 v3 = t2[s3 * 32 + lane];
        ax += (v0.x + v1.x) + (v2.x + v3.x);
        ay += (v0.y + v1.y) + (v2.y + v3.y);
    }
    for (; j < end; j++) {
        int s = __ldg(&g_csrc[j]);
        float2 v = t2[s * 32 + lane];
        ax += v.x;
        ay += v.y;
    }

    float2* o2 = (float2*)out;
    float2 cur = o2[(size_t)node * 32 + lane];
    cur.x += ax;
    cur.y += ay;
    o2[(size_t)node * 32 + lane] = cur;
}

// ---------------------------------------------------------------------------
extern "C" void kernel_launch(void* const* d_in, const int* in_sizes, int n_in,
                              void* d_out, int out_size)
{
    const float* x      = (const float*)d_in[0];
    const void*  eidx   = d_in[1];
    const float* W1root = (const float*)d_in[2];
    const float* W1nbr  = (const float*)d_in[3];
    const float* b1     = (const float*)d_in[4];
    const float* W2root = (const float*)d_in[5];
    const float* W2nbr  = (const float*)d_in[6];
    const float* b2     = (const float*)d_in[7];
    float* out = (float*)d_out;

    const int n = in_sizes[0] / DD;     // 50000
    const int E = in_sizes[1] / 2;      // 800000

    float *hptr, *tptr;
    cudaGetSymbolAddress((void**)&hptr, g_h);
    cudaGetSymbolAddress((void**)&tptr, g_t);

    const int edge_blocks = (E + 255) / 256;
    const int node_blocks = (n + 255) / 256;
    const int scan_blocks = (n + 255) / 256;
    const int gemm_blocks = (n + 127) / 128;
    const int agg_blocks  = (n * 32 + 255) / 256;

    // ---- CSR build ----
    detect_kernel<<<1, 128>>>((const unsigned*)eidx);
    zero_deg_kernel<<<node_blocks, 256>>>();
    convert_hist_kernel<<<edge_blocks, 256>>>(eidx, E);
    scan1_kernel<<<scan_blocks, 256>>>();
    scan2_kernel<<<1, 256>>>(scan_blocks);
    scan3_kernel<<<scan_blocks, 256>>>();
    fill_kernel<<<edge_blocks, 256>>>(E);

    // ---- Layer 1: h = x@W1r + b1 + agg(x@W1n) ----
    gemm_dual_kernel<false><<<gemm_blocks, 256>>>(x, W1root, W1nbr, b1, hptr, tptr, n);
    agg_kernel<<<agg_blocks, 256>>>(tptr, hptr, n);

    // ---- Layer 2: out = relu(h)@W2r + b2 + agg(relu(h)@W2n) ----
    gemm_dual_kernel<true><<<gemm_blocks, 256>>>(hptr, W2root, W2nbr, b2, out, tptr, n);
    agg_kernel<<<agg_blocks, 256>>>(tptr, out, n);
}

// round 5
// speedup vs baseline: 2.1522x; 1.1142x over previous
#include <cuda_runtime.h>
#include <cstdint>

#define NN 50000
#define DD 64
#define NE 800000

// ---- scratch (__device__ globals; allocation-free rule) ----
__device__ int   g_csrc[NE];     // CSR: source node per edge, grouped by dst
__device__ int   g_deg[NN];
__device__ int   g_off[NN + 1];
__device__ int   g_cur[NN];
__device__ int   g_bsum[256];
__device__ int   g_done;
__device__ __align__(16) float g_t[NN * DD];   // t = act(X) @ W_nbr
__device__ __align__(16) float g_h[NN * DD];   // hidden activations
__device__ int   g_idx64;

// ---------------------------------------------------------------------------
// Fused: zero g_deg, reset g_done, and (block 0) detect int64 vs int32
// edge_index (odd 32-bit words all zero => int64 high halves).
// ---------------------------------------------------------------------------
__global__ void prep_kernel(const unsigned* __restrict__ words) {
    int i = blockIdx.x * blockDim.x + threadIdx.x;
    if (i < NN) g_deg[i] = 0;
    if (i == 0) g_done = 0;
    if (blockIdx.x == 0) {
        __shared__ int any_nonzero;
        if (threadIdx.x == 0) any_nonzero = 0;
        __syncthreads();
        if (threadIdx.x < 128 && words[2 * threadIdx.x + 1] != 0u) any_nonzero = 1;
        __syncthreads();
        if (threadIdx.x == 0) g_idx64 = any_nonzero ? 0 : 1;
    }
}

// histogram of dst degrees (reads edge_index directly)
__global__ void hist_kernel(const void* __restrict__ idx, int E) {
    int i = blockIdx.x * blockDim.x + threadIdx.x;
    if (i >= E) return;
    int d;
    if (g_idx64) d = (int)((const long long*)idx)[(size_t)E + i];
    else         d = ((const int*)idx)[(size_t)E + i];
    atomicAdd(&g_deg[d], 1);
}

// ---- scan phase 1 (+ fused phase 2 via last-done block) ----
__global__ void scan1_kernel(int nblocks) {
    __shared__ int sh[256];
    int tid = threadIdx.x;
    int i = blockIdx.x * 256 + tid;
    int v = (i < NN) ? g_deg[i] : 0;
    sh[tid] = v;
    __syncthreads();
#pragma unroll
    for (int off = 1; off < 256; off <<= 1) {
        int x = (tid >= off) ? sh[tid - off] : 0;
        __syncthreads();
        sh[tid] += x;
        __syncthreads();
    }
    if (i < NN) g_off[i] = sh[tid] - v;          // exclusive within block
    if (tid == 255) g_bsum[blockIdx.x] = sh[255];

    // last-arriving block scans the block sums (exclusive) in-place
    __shared__ int is_last;
    __threadfence();
    if (tid == 0) is_last = (atomicAdd(&g_done, 1) == nblocks - 1) ? 1 : 0;
    __syncthreads();
    if (is_last) {
        int bv = (tid < nblocks) ? g_bsum[tid] : 0;
        sh[tid] = bv;
        __syncthreads();
#pragma unroll
        for (int off = 1; off < 256; off <<= 1) {
            int x = (tid >= off) ? sh[tid - off] : 0;
            __syncthreads();
            sh[tid] += x;
            __syncthreads();
        }
        if (tid < nblocks) g_bsum[tid] = sh[tid] - bv;
    }
}

__global__ void scan3_kernel() {
    int i = blockIdx.x * 256 + threadIdx.x;
    if (i < NN) {
        int o = g_off[i] + g_bsum[blockIdx.x];
        g_off[i] = o;
        g_cur[i] = o;
    }
    if (i == 0) g_off[NN] = NE;
}

// fill CSR source list (reads edge_index directly)
__global__ void fill_kernel(const void* __restrict__ idx, int E) {
    int e = blockIdx.x * blockDim.x + threadIdx.x;
    if (e >= E) return;
    int s, d;
    if (g_idx64) {
        const long long* p = (const long long*)idx;
        s = (int)p[e];
        d = (int)p[(size_t)E + e];
    } else {
        const int* p = (const int*)idx;
        s = p[e];
        d = p[(size_t)E + e];
    }
    int pos = atomicAdd(&g_cur[d], 1);
    g_csrc[pos] = s;
}

// ---------------------------------------------------------------------------
// Dual GEMM: Omain = act(X)@Wroot + b ; Ot = act(X)@Wnbr
// 128 rows/block, 256 threads. Thread tile: 4 rows x 8 cols x 2 matrices.
// X staged TRANSPOSED (sXT[k][r], stride 132 -> every float4 read 16B-aligned).
// ---------------------------------------------------------------------------
#define XT_STRIDE 132

template <bool RELU>
__global__ void __launch_bounds__(256, 2) gemm_dual_kernel(
    const float* __restrict__ X,
    const float* __restrict__ Wroot,
    const float* __restrict__ Wnbr,
    const float* __restrict__ bias,
    float* __restrict__ Omain,
    float* __restrict__ Ot,
    int n)
{
    __shared__ __align__(16) float sWr[64 * 64];
    __shared__ __align__(16) float sWn[64 * 64];
    __shared__ __align__(16) float sB[64];
    __shared__ __align__(16) float sXT[64 * XT_STRIDE];   // [k][row]

    const int tid = threadIdx.x;
    const int row0 = blockIdx.x * 128;

    // stage weights (1024 float4 each -> 4 per thread)
    {
        const float4* wr4 = (const float4*)Wroot;
        const float4* wn4 = (const float4*)Wnbr;
        float4* swr4 = (float4*)sWr;
        float4* swn4 = (float4*)sWn;
#pragma unroll
        for (int i = 0; i < 4; i++) {
            swr4[tid + 256 * i] = wr4[tid + 256 * i];
            swn4[tid + 256 * i] = wn4[tid + 256 * i];
        }
        if (tid < 64) sB[tid] = bias[tid];
    }

    // stage X transposed: 128 rows x 16 float4-chunks = 2048 chunks, 8/thread
#pragma unroll
    for (int i = 0; i < 8; i++) {
        int idx = tid + 256 * i;      // 0..2047
        int r = idx >> 4;             // local row 0..127
        int c4 = idx & 15;            // float4 chunk 0..15
        int grow = row0 + r;
        float4 v = make_float4(0.f, 0.f, 0.f, 0.f);
        if (grow < n) v = ((const float4*)X)[(size_t)grow * 16 + c4];
        if (RELU) {
            v.x = fmaxf(v.x, 0.f); v.y = fmaxf(v.y, 0.f);
            v.z = fmaxf(v.z, 0.f); v.w = fmaxf(v.w, 0.f);
        }
        sXT[(c4 * 4 + 0) * XT_STRIDE + r] = v.x;
        sXT[(c4 * 4 + 1) * XT_STRIDE + r] = v.y;
        sXT[(c4 * 4 + 2) * XT_STRIDE + r] = v.z;
        sXT[(c4 * 4 + 3) * XT_STRIDE + r] = v.w;
    }
    __syncthreads();

    const int cseg = tid & 7;        // cols [cseg*8, cseg*8+8)
    const int rowgrp = tid >> 3;     // rows [rowgrp*4, rowgrp*4+4)

    float4 ar[4][2], an[4][2];
    {
        float4 b0 = *(const float4*)&sB[cseg * 8];
        float4 b1 = *(const float4*)&sB[cseg * 8 + 4];
#pragma unroll
        for (int j = 0; j < 4; j++) {
            ar[j][0] = b0; ar[j][1] = b1;
            an[j][0] = make_float4(0.f, 0.f, 0.f, 0.f);
            an[j][1] = make_float4(0.f, 0.f, 0.f, 0.f);
        }
    }

#pragma unroll 8
    for (int k = 0; k < 64; k++) {
        float4 xv = *(const float4*)&sXT[k * XT_STRIDE + rowgrp * 4];
        float4 wr0 = *(const float4*)&sWr[k * 64 + cseg * 8];
        float4 wr1 = *(const float4*)&sWr[k * 64 + cseg * 8 + 4];
        float4 wn0 = *(const float4*)&sWn[k * 64 + cseg * 8];
        float4 wn1 = *(const float4*)&sWn[k * 64 + cseg * 8 + 4];
        const float xs[4] = {xv.x, xv.y, xv.z, xv.w};
#pragma unroll
        for (int j = 0; j < 4; j++) {
            float xvj = xs[j];
            ar[j][0].x = fmaf(xvj, wr0.x, ar[j][0].x);
            ar[j][0].y = fmaf(xvj, wr0.y, ar[j][0].y);
            ar[j][0].z = fmaf(xvj, wr0.z, ar[j][0].z);
            ar[j][0].w = fmaf(xvj, wr0.w, ar[j][0].w);
            ar[j][1].x = fmaf(xvj, wr1.x, ar[j][1].x);
            ar[j][1].y = fmaf(xvj, wr1.y, ar[j][1].y);
            ar[j][1].z = fmaf(xvj, wr1.z, ar[j][1].z);
            ar[j][1].w = fmaf(xvj, wr1.w, ar[j][1].w);
            an[j][0].x = fmaf(xvj, wn0.x, an[j][0].x);
            an[j][0].y = fmaf(xvj, wn0.y, an[j][0].y);
            an[j][0].z = fmaf(xvj, wn0.z, an[j][0].z);
            an[j][0].w = fmaf(xvj, wn0.w, an[j][0].w);
            an[j][1].x = fmaf(xvj, wn1.x, an[j][1].x);
            an[j][1].y = fmaf(xvj, wn1.y, an[j][1].y);
            an[j][1].z = fmaf(xvj, wn1.z, an[j][1].z);
            an[j][1].w = fmaf(xvj, wn1.w, an[j][1].w);
        }
    }

#pragma unroll
    for (int j = 0; j < 4; j++) {
        int grow = row0 + rowgrp * 4 + j;
        if (grow < n) {
            float4* om = (float4*)(Omain + (size_t)grow * 64 + cseg * 8);
            om[0] = ar[j][0]; om[1] = ar[j][1];
            float4* ot = (float4*)(Ot + (size_t)grow * 64 + cseg * 8);
            ot[0] = an[j][0]; ot[1] = an[j][1];
        }
    }
}

// ---------------------------------------------------------------------------
// CSR gather-aggregate: HALF-WARP per node, float4 per lane (16 x 16B = row).
// out[i] += sum_{e: dst==i} t[csrc[e]] ; unroll-4 => 4 independent 250-cyc
// L2 loads in flight per half-warp, 2 nodes per warp.
// ---------------------------------------------------------------------------
__global__ void __launch_bounds__(256) agg_kernel(
    const float* __restrict__ t, float* __restrict__ out, int n)
{
    int gid = blockIdx.x * blockDim.x + threadIdx.x;
    int node = gid >> 4;
    if (node >= n) return;
    int part = threadIdx.x & 15;

    int start = g_off[node];
    int end   = g_off[node + 1];

    const float4* t4 = (const float4*)t;
    float4 acc = make_float4(0.f, 0.f, 0.f, 0.f);

    int j = start;
    for (; j + 4 <= end; j += 4) {
        int s0 = __ldg(&g_csrc[j]);
        int s1 = __ldg(&g_csrc[j + 1]);
        int s2 = __ldg(&g_csrc[j + 2]);
        int s3 = __ldg(&g_csrc[j + 3]);
        float4 v0 = t4[(size_t)s0 * 16 + part];
        float4 v1 = t4[(size_t)s1 * 16 + part];
        float4 v2 = t4[(size_t)s2 * 16 + part];
        float4 v3 = t4[(size_t)s3 * 16 + part];
        acc.x += (v0.x + v1.x) + (v2.x + v3.x);
        acc.y += (v0.y + v1.y) + (v2.y + v3.y);
        acc.z += (v0.z + v1.z) + (v2.z + v3.z);
        acc.w += (v0.w + v1.w) + (v2.w + v3.w);
    }
    for (; j < end; j++) {
        int s = __ldg(&g_csrc[j]);
        float4 v = t4[(size_t)s * 16 + part];
        acc.x += v.x; acc.y += v.y; acc.z += v.z; acc.w += v.w;
    }

    float4* o4 = (float4*)out;
    float4 cur = o4[(size_t)node * 16 + part];
    cur.x += acc.x; cur.y += acc.y; cur.z += acc.z; cur.w += acc.w;
    o4[(size_t)node * 16 + part] = cur;
}

// ---------------------------------------------------------------------------
extern "C" void kernel_launch(void* const* d_in, const int* in_sizes, int n_in,
                              void* d_out, int out_size)
{
    const float* x      = (const float*)d_in[0];
    const void*  eidx   = d_in[1];
    const float* W1root = (const float*)d_in[2];
    const float* W1nbr  = (const float*)d_in[3];
    const float* b1     = (const float*)d_in[4];
    const float* W2root = (const float*)d_in[5];
    const float* W2nbr  = (const float*)d_in[6];
    const float* b2     = (const float*)d_in[7];
    float* out = (float*)d_out;

    const int n = in_sizes[0] / DD;     // 50000
    const int E = in_sizes[1] / 2;      // 800000

    float *hptr, *tptr;
    cudaGetSymbolAddress((void**)&hptr, g_h);
    cudaGetSymbolAddress((void**)&tptr, g_t);

    const int edge_blocks = (E + 255) / 256;
    const int scan_blocks = (n + 255) / 256;          // 196
    const int gemm_blocks = (n + 127) / 128;
    const int agg_blocks  = (n * 16 + 255) / 256;

    // ---- CSR build (5 launches) ----
    prep_kernel<<<scan_blocks, 256>>>((const unsigned*)eidx);
    hist_kernel<<<edge_blocks, 256>>>(eidx, E);
    scan1_kernel<<<scan_blocks, 256>>>(scan_blocks);
    scan3_kernel<<<scan_blocks, 256>>>();
    fill_kernel<<<edge_blocks, 256>>>(eidx, E);

    // ---- Layer 1: h = x@W1r + b1 + agg(x@W1n) ----
    gemm_dual_kernel<false><<<gemm_blocks, 256>>>(x, W1root, W1nbr, b1, hptr, tptr, n);
    agg_kernel<<<agg_blocks, 256>>>(tptr, hptr, n);

    // ---- Layer 2: out = relu(h)@W2r + b2 + agg(relu(h)@W2n) ----
    gemm_dual_kernel<true><<<gemm_blocks, 256>>>(hptr, W2root, W2nbr, b2, out, tptr, n);
    agg_kernel<<<agg_blocks, 256>>>(tptr, out, n);
}

// round 6
// speedup vs baseline: 2.3153x; 1.0758x over previous
#include <cuda_runtime.h>
#include <cstdint>

#define NN 50000
#define DD 64
#define NE 800000

// ---- scratch (__device__ globals; allocation-free rule) ----
__device__ int   g_csrc[NE];     // CSR: source node per edge, grouped by dst
__device__ int   g_deg[NN];      // invariant: zero at entry of every call
__device__ int   g_off[NN + 1];
__device__ int   g_cur[NN];
__device__ int   g_bsum[256];
__device__ int   g_done;         // invariant: zero at entry of every call
__device__ __align__(16) float g_t[NN * DD];   // t = act(X) @ W_nbr
__device__ __align__(16) float g_h[NN * DD];   // hidden activations

// ---------------------------------------------------------------------------
// Per-block int64-vs-int32 detection: sample the first 256 odd 32-bit words.
// int64 little-endian high halves (indices < 50000) are all zero; for int32
// they are real indices (P[all 256 zero] ~ (2e-5)^256 ~ 0).
// Returns 1 if buffer is int64. Costs 2 bar.sync.
// ---------------------------------------------------------------------------
__device__ __forceinline__ int detect_idx64(const unsigned* words) {
    __shared__ int nz;
    if (threadIdx.x == 0) nz = 0;
    __syncthreads();
    if (threadIdx.x < 256 && words[2 * threadIdx.x + 1] != 0u) nz = 1;
    __syncthreads();
    return nz ? 0 : 1;
}

// histogram of dst degrees (reads edge_index directly)
__global__ void hist_kernel(const void* __restrict__ idx, int E) {
    int idx64 = detect_idx64((const unsigned*)idx);
    int i = blockIdx.x * blockDim.x + threadIdx.x;
    if (i >= E) return;
    int d;
    if (idx64) d = (int)((const long long*)idx)[(size_t)E + i];
    else       d = ((const int*)idx)[(size_t)E + i];
    atomicAdd(&g_deg[d], 1);
}

// ---- scan phase 1 (+ fused phase 2 via last-done block) ----
__global__ void scan1_kernel(int nblocks) {
    __shared__ int sh[256];
    int tid = threadIdx.x;
    int i = blockIdx.x * 256 + tid;
    int v = (i < NN) ? g_deg[i] : 0;
    sh[tid] = v;
    __syncthreads();
#pragma unroll
    for (int off = 1; off < 256; off <<= 1) {
        int x = (tid >= off) ? sh[tid - off] : 0;
        __syncthreads();
        sh[tid] += x;
        __syncthreads();
    }
    if (i < NN) g_off[i] = sh[tid] - v;          // exclusive within block
    if (tid == 255) g_bsum[blockIdx.x] = sh[255];

    // last-arriving block scans the block sums (exclusive) in-place
    __shared__ int is_last;
    __threadfence();
    if (tid == 0) is_last = (atomicAdd(&g_done, 1) == nblocks - 1) ? 1 : 0;
    __syncthreads();
    if (is_last) {
        int bv = (tid < nblocks) ? g_bsum[tid] : 0;
        sh[tid] = bv;
        __syncthreads();
#pragma unroll
        for (int off = 1; off < 256; off <<= 1) {
            int x = (tid >= off) ? sh[tid - off] : 0;
            __syncthreads();
            sh[tid] += x;
            __syncthreads();
        }
        if (tid < nblocks) g_bsum[tid] = sh[tid] - bv;
    }
}

// add block offsets; also restore g_deg=0 and g_done=0 for the next call
__global__ void scan3_kernel() {
    int i = blockIdx.x * 256 + threadIdx.x;
    if (i < NN) {
        int o = g_off[i] + g_bsum[blockIdx.x];
        g_off[i] = o;
        g_cur[i] = o;
        g_deg[i] = 0;
    }
    if (i == 0) { g_off[NN] = NE; g_done = 0; }
}

// fill CSR source list (reads edge_index directly)
__global__ void fill_kernel(const void* __restrict__ idx, int E) {
    int idx64 = detect_idx64((const unsigned*)idx);
    int e = blockIdx.x * blockDim.x + threadIdx.x;
    if (e >= E) return;
    int s, d;
    if (idx64) {
        const long long* p = (const long long*)idx;
        s = (int)p[e];
        d = (int)p[(size_t)E + e];
    } else {
        const int* p = (const int*)idx;
        s = p[e];
        d = p[(size_t)E + e];
    }
    int pos = atomicAdd(&g_cur[d], 1);
    g_csrc[pos] = s;
}

// ---------------------------------------------------------------------------
// Dual GEMM: Omain = act(X)@Wroot + b ; Ot = act(X)@Wnbr
// 128 rows/block, 256 threads. Thread tile: 4 rows x 8 cols x 2 matrices.
// X staged TRANSPOSED (sXT[k][r], stride 132 -> every float4 read 16B-aligned).
// ---------------------------------------------------------------------------
#define XT_STRIDE 132

template <bool RELU>
__global__ void __launch_bounds__(256, 2) gemm_dual_kernel(
    const float* __restrict__ X,
    const float* __restrict__ Wroot,
    const float* __restrict__ Wnbr,
    const float* __restrict__ bias,
    float* __restrict__ Omain,
    float* __restrict__ Ot,
    int n)
{
    __shared__ __align__(16) float sWr[64 * 64];
    __shared__ __align__(16) float sWn[64 * 64];
    __shared__ __align__(16) float sB[64];
    __shared__ __align__(16) float sXT[64 * XT_STRIDE];   // [k][row]

    const int tid = threadIdx.x;
    const int row0 = blockIdx.x * 128;

    // stage weights (1024 float4 each -> 4 per thread)
    {
        const float4* wr4 = (const float4*)Wroot;
        const float4* wn4 = (const float4*)Wnbr;
        float4* swr4 = (float4*)sWr;
        float4* swn4 = (float4*)sWn;
#pragma unroll
        for (int i = 0; i < 4; i++) {
            swr4[tid + 256 * i] = wr4[tid + 256 * i];
            swn4[tid + 256 * i] = wn4[tid + 256 * i];
        }
        if (tid < 64) sB[tid] = bias[tid];
    }

    // stage X transposed: 128 rows x 16 float4-chunks = 2048 chunks, 8/thread
#pragma unroll
    for (int i = 0; i < 8; i++) {
        int idx = tid + 256 * i;      // 0..2047
        int r = idx >> 4;             // local row 0..127
        int c4 = idx & 15;            // float4 chunk 0..15
        int grow = row0 + r;
        float4 v = make_float4(0.f, 0.f, 0.f, 0.f);
        if (grow < n) v = ((const float4*)X)[(size_t)grow * 16 + c4];
        if (RELU) {
            v.x = fmaxf(v.x, 0.f); v.y = fmaxf(v.y, 0.f);
            v.z = fmaxf(v.z, 0.f); v.w = fmaxf(v.w, 0.f);
        }
        sXT[(c4 * 4 + 0) * XT_STRIDE + r] = v.x;
        sXT[(c4 * 4 + 1) * XT_STRIDE + r] = v.y;
        sXT[(c4 * 4 + 2) * XT_STRIDE + r] = v.z;
        sXT[(c4 * 4 + 3) * XT_STRIDE + r] = v.w;
    }
    __syncthreads();

    const int cseg = tid & 7;        // cols [cseg*8, cseg*8+8)
    const int rowgrp = tid >> 3;     // rows [rowgrp*4, rowgrp*4+4)

    float4 ar[4][2], an[4][2];
    {
        float4 b0 = *(const float4*)&sB[cseg * 8];
        float4 b1 = *(const float4*)&sB[cseg * 8 + 4];
#pragma unroll
        for (int j = 0; j < 4; j++) {
            ar[j][0] = b0; ar[j][1] = b1;
            an[j][0] = make_float4(0.f, 0.f, 0.f, 0.f);
            an[j][1] = make_float4(0.f, 0.f, 0.f, 0.f);
        }
    }

#pragma unroll 8
    for (int k = 0; k < 64; k++) {
        float4 xv = *(const float4*)&sXT[k * XT_STRIDE + rowgrp * 4];
        float4 wr0 = *(const float4*)&sWr[k * 64 + cseg * 8];
        float4 wr1 = *(const float4*)&sWr[k * 64 + cseg * 8 + 4];
        float4 wn0 = *(const float4*)&sWn[k * 64 + cseg * 8];
        float4 wn1 = *(const float4*)&sWn[k * 64 + cseg * 8 + 4];
        const float xs[4] = {xv.x, xv.y, xv.z, xv.w};
#pragma unroll
        for (int j = 0; j < 4; j++) {
            float xvj = xs[j];
            ar[j][0].x = fmaf(xvj, wr0.x, ar[j][0].x);
            ar[j][0].y = fmaf(xvj, wr0.y, ar[j][0].y);
            ar[j][0].z = fmaf(xvj, wr0.z, ar[j][0].z);
            ar[j][0].w = fmaf(xvj, wr0.w, ar[j][0].w);
            ar[j][1].x = fmaf(xvj, wr1.x, ar[j][1].x);
            ar[j][1].y = fmaf(xvj, wr1.y, ar[j][1].y);
            ar[j][1].z = fmaf(xvj, wr1.z, ar[j][1].z);
            ar[j][1].w = fmaf(xvj, wr1.w, ar[j][1].w);
            an[j][0].x = fmaf(xvj, wn0.x, an[j][0].x);
            an[j][0].y = fmaf(xvj, wn0.y, an[j][0].y);
            an[j][0].z = fmaf(xvj, wn0.z, an[j][0].z);
            an[j][0].w = fmaf(xvj, wn0.w, an[j][0].w);
            an[j][1].x = fmaf(xvj, wn1.x, an[j][1].x);
            an[j][1].y = fmaf(xvj, wn1.y, an[j][1].y);
            an[j][1].z = fmaf(xvj, wn1.z, an[j][1].z);
            an[j][1].w = fmaf(xvj, wn1.w, an[j][1].w);
        }
    }

#pragma unroll
    for (int j = 0; j < 4; j++) {
        int grow = row0 + rowgrp * 4 + j;
        if (grow < n) {
            float4* om = (float4*)(Omain + (size_t)grow * 64 + cseg * 8);
            om[0] = ar[j][0]; om[1] = ar[j][1];
            float4* ot = (float4*)(Ot + (size_t)grow * 64 + cseg * 8);
            ot[0] = an[j][0]; ot[1] = an[j][1];
        }
    }
}

// ---------------------------------------------------------------------------
// CSR gather-aggregate: HALF-WARP per node, float4 per lane (16 x 16B = row).
// out[i] += sum_{e: dst==i} t[csrc[e]]
// ---------------------------------------------------------------------------
__global__ void __launch_bounds__(256) agg_kernel(
    const float* __restrict__ t, float* __restrict__ out, int n)
{
    int gid = blockIdx.x * blockDim.x + threadIdx.x;
    int node = gid >> 4;
    if (node >= n) return;
    int part = threadIdx.x & 15;

    int start = g_off[node];
    int end   = g_off[node + 1];

    const float4* t4 = (const float4*)t;
    float4 acc = make_float4(0.f, 0.f, 0.f, 0.f);

    int j = start;
    for (; j + 4 <= end; j += 4) {
        int s0 = __ldg(&g_csrc[j]);
        int s1 = __ldg(&g_csrc[j + 1]);
        int s2 = __ldg(&g_csrc[j + 2]);
        int s3 = __ldg(&g_csrc[j + 3]);
        float4 v0 = t4[(size_t)s0 * 16 + part];
        float4 v1 = t4[(size_t)s1 * 16 + part];
        float4 v2 = t4[(size_t)s2 * 16 + part];
        float4 v3 = t4[(size_t)s3 * 16 + part];
        acc.x += (v0.x + v1.x) + (v2.x + v3.x);
        acc.y += (v0.y + v1.y) + (v2.y + v3.y);
        acc.z += (v0.z + v1.z) + (v2.z + v3.z);
        acc.w += (v0.w + v1.w) + (v2.w + v3.w);
    }
    for (; j < end; j++) {
        int s = __ldg(&g_csrc[j]);
        float4 v = t4[(size_t)s * 16 + part];
        acc.x += v.x; acc.y += v.y; acc.z += v.z; acc.w += v.w;
    }

    float4* o4 = (float4*)out;
    float4 cur = o4[(size_t)node * 16 + part];
    cur.x += acc.x; cur.y += acc.y; cur.z += acc.z; cur.w += acc.w;
    o4[(size_t)node * 16 + part] = cur;
}

// ---------------------------------------------------------------------------
extern "C" void kernel_launch(void* const* d_in, const int* in_sizes, int n_in,
                              void* d_out, int out_size)
{
    const float* x      = (const float*)d_in[0];
    const void*  eidx   = d_in[1];
    const float* W1root = (const float*)d_in[2];
    const float* W1nbr  = (const float*)d_in[3];
    const float* b1     = (const float*)d_in[4];
    const float* W2root = (const float*)d_in[5];
    const float* W2nbr  = (const float*)d_in[6];
    const float* b2     = (const float*)d_in[7];
    float* out = (float*)d_out;

    const int n = in_sizes[0] / DD;     // 50000
    const int E = in_sizes[1] / 2;      // 800000

    float *hptr, *tptr;
    cudaGetSymbolAddress((void**)&hptr, g_h);
    cudaGetSymbolAddress((void**)&tptr, g_t);

    const int edge_blocks = (E + 255) / 256;
    const int scan_blocks = (n + 255) / 256;          // 196
    const int gemm_blocks = (n + 127) / 128;
    const int agg_blocks  = (n * 16 + 255) / 256;

    // Side stream + events for graph-level parallelism (host-side resources
    // only; created once, reused — identical captured work every call).
    static cudaStream_t s_side = nullptr;
    static cudaEvent_t  ev_fork = nullptr, ev_join = nullptr;
    if (s_side == nullptr) {
        cudaStreamCreateWithFlags(&s_side, cudaStreamNonBlocking);
        cudaEventCreateWithFlags(&ev_fork, cudaEventDisableTiming);
        cudaEventCreateWithFlags(&ev_join, cudaEventDisableTiming);
    }

    // ---- fork: CSR build on side stream, concurrent with gemm1 ----
    cudaEventRecord(ev_fork, cudaStreamPerThread);
    cudaStreamWaitEvent(s_side, ev_fork, 0);

    hist_kernel <<<edge_blocks, 256, 0, s_side>>>(eidx, E);
    scan1_kernel<<<scan_blocks, 256, 0, s_side>>>(scan_blocks);
    scan3_kernel<<<scan_blocks, 256, 0, s_side>>>();
    fill_kernel <<<edge_blocks, 256, 0, s_side>>>(eidx, E);
    cudaEventRecord(ev_join, s_side);

    // ---- main stream: layer-1 GEMM in parallel with CSR build ----
    gemm_dual_kernel<false><<<gemm_blocks, 256>>>(x, W1root, W1nbr, b1, hptr, tptr, n);

    // join: agg1 needs both CSR and t1
    cudaStreamWaitEvent(cudaStreamPerThread, ev_join, 0);
    agg_kernel<<<agg_blocks, 256>>>(tptr, hptr, n);

    // ---- Layer 2 ----
    gemm_dual_kernel<true><<<gemm_blocks, 256>>>(hptr, W2root, W2nbr, b2, out, tptr, n);
    agg_kernel<<<agg_blocks, 256>>>(tptr, out, n);
}